// round 1
// baseline (speedup 1.0000x reference)
#include <cuda_runtime.h>

#define BATCH 4
#define SEQ   4096
#define HID   1024
#define NST   16
#define NROWS (BATCH*SEQ)       // 16384
#define CHUNK 64
#define NCH   (SEQ/CHUNK)       // 64 chunks per batch
#define NCHT  (BATCH*NCH)       // 256 total chunks
#define LN_EPS 1e-5f

// ---- scratch (static device globals; no allocation) ----
__device__ float g_xB[NROWS*NST];                  // x @ B^T          1 MB
__device__ float g_states[NROWS*NST];              // scan states      1 MB
__device__ float g_finals[NCHT*NST];               // per-chunk local finals
__device__ float g_carry[NCHT*NST];                // carry-in per chunk
__device__ float g_Apow[(CHUNK+1)*NST*NST];        // A^0 .. A^64

// ============================================================
// K1: xB[row,n] = sum_h x[row,h] * B[n,h]     (row = b*SEQ+s)
// block: 256 thr, 128 rows; K-tiled through smem
// ============================================================
__global__ __launch_bounds__(256) void k_xB(const float* __restrict__ x,
                                            const float* __restrict__ B) {
    __shared__ float xs[128][33];
    __shared__ float Bs[NST][33];
    const int tid = threadIdx.x;
    const int rowbase = blockIdx.x * 128;
    const int n  = tid & 15;     // output state index
    const int rg = tid >> 4;     // row group (8 rows each)

    float acc[8];
#pragma unroll
    for (int i = 0; i < 8; i++) acc[i] = 0.f;

    for (int kb = 0; kb < HID; kb += 32) {
#pragma unroll
        for (int p = 0; p < 4; p++) {
            int idx = tid + p * 256;         // float4 index, 1024 total
            int r  = idx >> 3;
            int kq = (idx & 7) * 4;
            float4 v = *(const float4*)&x[(rowbase + r) * HID + kb + kq];
            xs[r][kq+0] = v.x; xs[r][kq+1] = v.y; xs[r][kq+2] = v.z; xs[r][kq+3] = v.w;
        }
        if (tid < 128) {
            int bn = tid >> 3;
            int kq = (tid & 7) * 4;
            float4 v = *(const float4*)&B[bn * HID + kb + kq];
            Bs[bn][kq+0] = v.x; Bs[bn][kq+1] = v.y; Bs[bn][kq+2] = v.z; Bs[bn][kq+3] = v.w;
        }
        __syncthreads();
#pragma unroll
        for (int k = 0; k < 32; k++) {
            float bv = Bs[n][k];
#pragma unroll
            for (int r = 0; r < 8; r++) acc[r] += xs[rg*8 + r][k] * bv;
        }
        __syncthreads();
    }
#pragma unroll
    for (int r = 0; r < 8; r++)
        g_xB[(rowbase + rg*8 + r) * NST + n] = acc[r];
}

// ============================================================
// K2a: per-chunk local scans (zero initial state), store local
// states into g_states and chunk-final into g_finals.
// 16 lanes per chunk; 8 chunks per 128-thread block.
// ============================================================
__global__ __launch_bounds__(128) void k_scan_local(const float* __restrict__ A) {
    const int tid = threadIdx.x;
    const int lane16 = tid & 15;
    const int cid = blockIdx.x * 8 + (tid >> 4);   // 0..255
    const int b = cid >> 6;
    const int c = cid & (NCH - 1);
    const int gb = tid & 16;                        // group base within warp

    float Arow[NST];
#pragma unroll
    for (int k = 0; k < NST; k++) Arow[k] = A[lane16 * NST + k];

    float s = 0.f;
    const int base = (b * SEQ + c * CHUNK) * NST;
    for (int i = 0; i < CHUNK; i++) {
        float u  = g_xB[base + i * NST + lane16];
        float ns = u;
#pragma unroll
        for (int k = 0; k < NST; k++)
            ns += Arow[k] * __shfl_sync(0xffffffffu, s, gb | k, 32);
        s = ns;
        g_states[base + i * NST + lane16] = s;
    }
    g_finals[cid * NST + lane16] = s;
}

// ============================================================
// K2b: A^0..A^CHUNK  (single block, 256 thr)
// ============================================================
__global__ __launch_bounds__(256) void k_powers(const float* __restrict__ A) {
    __shared__ float As[256], P[256];
    const int t = threadIdx.x;
    As[t] = A[t];
    float id = ((t >> 4) == (t & 15)) ? 1.f : 0.f;
    P[t] = id;
    g_Apow[t] = id;
    __syncthreads();
    const int n = t >> 4, m = t & 15;
    for (int j = 1; j <= CHUNK; j++) {
        float v = 0.f;
#pragma unroll
        for (int k = 0; k < NST; k++) v += As[n * NST + k] * P[k * NST + m];
        __syncthreads();
        P[t] = v;
        g_Apow[j * 256 + t] = v;
        __syncthreads();
    }
}

// ============================================================
// K2c: sequential carry across chunks per batch (64 thr: 4 batches x 16)
// carry[b,0]=0; carry[b,c] = A^CHUNK * carry[b,c-1] + finals[b,c-1]
// ============================================================
__global__ __launch_bounds__(64) void k_carry() {
    const int t = threadIdx.x;
    const int b = t >> 4;
    const int n = t & 15;
    const int gb = t & 16;

    float Prow[NST];
#pragma unroll
    for (int k = 0; k < NST; k++) Prow[k] = g_Apow[CHUNK * 256 + n * NST + k];

    float s = 0.f;
    g_carry[(b * NCH + 0) * NST + n] = 0.f;
    for (int c = 1; c < NCH; c++) {
        float f  = g_finals[(b * NCH + c - 1) * NST + n];
        float ns = f;
#pragma unroll
        for (int k = 0; k < NST; k++)
            ns += Prow[k] * __shfl_sync(0xffffffffu, s, gb | k, 32);
        s = ns;
        g_carry[(b * NCH + c) * NST + n] = s;
    }
}

// ============================================================
// K2d: fix-up: states[b, c*CHUNK + i] += A^{i+1} @ carry[b,c]
// one 16-lane group per row
// ============================================================
__global__ __launch_bounds__(128) void k_fixup() {
    const int tid = threadIdx.x;
    const int n  = tid & 15;
    const int gb = tid & 16;
    const int row = blockIdx.x * 8 + (tid >> 4);
    const int b  = row >> 12;             // / SEQ
    const int tt = row & (SEQ - 1);
    const int c  = tt >> 6;               // / CHUNK
    const int i  = tt & (CHUNK - 1);

    float cv = g_carry[(b * NCH + c) * NST + n];
    const float* Pr = &g_Apow[(i + 1) * 256 + n * NST];
    float v = 0.f;
#pragma unroll
    for (int k = 0; k < NST; k++)
        v += Pr[k] * __shfl_sync(0xffffffffu, cv, gb | k, 32);
    g_states[row * NST + n] += v;
}

// ============================================================
// K3: out = x @ D^T + states @ C^T     (pre-LayerNorm)
// SGEMM: M=16384 N=1024 K=1024(+16), BM=BN=128 BK=16, 8x8/thread
// ============================================================
#define BM 128
#define BN 128
#define BK 16

__global__ __launch_bounds__(256) void k_main(const float* __restrict__ x,
                                              const float* __restrict__ C,
                                              const float* __restrict__ D,
                                              float* __restrict__ out) {
    __shared__ float As[BK][BM + 4];
    __shared__ float Bs[BK][BN + 4];
    const int tid = threadIdx.x;
    const int rowbase = blockIdx.y * BM;
    const int colbase = blockIdx.x * BN;
    const int tx = tid & 15;
    const int ty = tid >> 4;
    const int lr = tid >> 1;             // load row/col 0..127
    const int kq = (tid & 1) * 8;        // 0 or 8

    float acc[8][8];
#pragma unroll
    for (int i = 0; i < 8; i++)
#pragma unroll
        for (int j = 0; j < 8; j++) acc[i][j] = 0.f;

#define COMPUTE16()                                                          \
    {                                                                        \
        _Pragma("unroll")                                                    \
        for (int k = 0; k < BK; k++) {                                       \
            float4 a0 = *(const float4*)&As[k][ty * 8];                      \
            float4 a1 = *(const float4*)&As[k][ty * 8 + 4];                  \
            float4 b0 = *(const float4*)&Bs[k][tx * 8];                      \
            float4 b1 = *(const float4*)&Bs[k][tx * 8 + 4];                  \
            float av[8] = {a0.x, a0.y, a0.z, a0.w, a1.x, a1.y, a1.z, a1.w};  \
            float bv[8] = {b0.x, b0.y, b0.z, b0.w, b1.x, b1.y, b1.z, b1.w};  \
            _Pragma("unroll")                                                \
            for (int i = 0; i < 8; i++)                                      \
                _Pragma("unroll")                                            \
                for (int j = 0; j < 8; j++) acc[i][j] += av[i] * bv[j];      \
        }                                                                    \
    }

    // ---- phase 0: states @ C^T (exactly BK=16 deep) ----
    {
        float4 a0 = *(const float4*)&g_states[(rowbase + lr) * NST + kq];
        float4 a1 = *(const float4*)&g_states[(rowbase + lr) * NST + kq + 4];
        float4 b0 = *(const float4*)&C[(colbase + lr) * NST + kq];
        float4 b1 = *(const float4*)&C[(colbase + lr) * NST + kq + 4];
        As[kq+0][lr]=a0.x; As[kq+1][lr]=a0.y; As[kq+2][lr]=a0.z; As[kq+3][lr]=a0.w;
        As[kq+4][lr]=a1.x; As[kq+5][lr]=a1.y; As[kq+6][lr]=a1.z; As[kq+7][lr]=a1.w;
        Bs[kq+0][lr]=b0.x; Bs[kq+1][lr]=b0.y; Bs[kq+2][lr]=b0.z; Bs[kq+3][lr]=b0.w;
        Bs[kq+4][lr]=b1.x; Bs[kq+5][lr]=b1.y; Bs[kq+6][lr]=b1.z; Bs[kq+7][lr]=b1.w;
        __syncthreads();
        COMPUTE16();
        __syncthreads();
    }

    // ---- main loop: x @ D^T ----
    for (int kt = 0; kt < HID; kt += BK) {
        float4 a0 = *(const float4*)&x[(size_t)(rowbase + lr) * HID + kt + kq];
        float4 a1 = *(const float4*)&x[(size_t)(rowbase + lr) * HID + kt + kq + 4];
        float4 b0 = *(const float4*)&D[(size_t)(colbase + lr) * HID + kt + kq];
        float4 b1 = *(const float4*)&D[(size_t)(colbase + lr) * HID + kt + kq + 4];
        As[kq+0][lr]=a0.x; As[kq+1][lr]=a0.y; As[kq+2][lr]=a0.z; As[kq+3][lr]=a0.w;
        As[kq+4][lr]=a1.x; As[kq+5][lr]=a1.y; As[kq+6][lr]=a1.z; As[kq+7][lr]=a1.w;
        Bs[kq+0][lr]=b0.x; Bs[kq+1][lr]=b0.y; Bs[kq+2][lr]=b0.z; Bs[kq+3][lr]=b0.w;
        Bs[kq+4][lr]=b1.x; Bs[kq+5][lr]=b1.y; Bs[kq+6][lr]=b1.z; Bs[kq+7][lr]=b1.w;
        __syncthreads();
        COMPUTE16();
        __syncthreads();
    }

#pragma unroll
    for (int i = 0; i < 8; i++) {
        int row = rowbase + ty * 8 + i;
        float4 o0 = make_float4(acc[i][0], acc[i][1], acc[i][2], acc[i][3]);
        float4 o1 = make_float4(acc[i][4], acc[i][5], acc[i][6], acc[i][7]);
        *(float4*)&out[(size_t)row * HID + colbase + tx * 8]     = o0;
        *(float4*)&out[(size_t)row * HID + colbase + tx * 8 + 4] = o1;
    }
#undef COMPUTE16
}

// ============================================================
// K4: LayerNorm in place over last dim (H=1024), 1 block / row
// ============================================================
__global__ __launch_bounds__(256) void k_ln(float* __restrict__ out,
                                            const float* __restrict__ gamma,
                                            const float* __restrict__ beta) {
    __shared__ float rs[8], rs2[8];
    const int row = blockIdx.x;
    const int tid = threadIdx.x;

    float4 v = *(const float4*)&out[(size_t)row * HID + tid * 4];
    float s  = v.x + v.y + v.z + v.w;
    float s2 = v.x*v.x + v.y*v.y + v.z*v.z + v.w*v.w;
#pragma unroll
    for (int o = 16; o > 0; o >>= 1) {
        s  += __shfl_down_sync(0xffffffffu, s,  o);
        s2 += __shfl_down_sync(0xffffffffu, s2, o);
    }
    if ((tid & 31) == 0) { rs[tid >> 5] = s; rs2[tid >> 5] = s2; }
    __syncthreads();
    float ts = 0.f, ts2 = 0.f;
#pragma unroll
    for (int i = 0; i < 8; i++) { ts += rs[i]; ts2 += rs2[i]; }

    const float mu  = ts * (1.f / HID);
    const float var = ts2 * (1.f / HID) - mu * mu;
    const float inv = rsqrtf(var + LN_EPS);

    float4 g = *(const float4*)&gamma[tid * 4];
    float4 b = *(const float4*)&beta[tid * 4];
    v.x = (v.x - mu) * inv * g.x + b.x;
    v.y = (v.y - mu) * inv * g.y + b.y;
    v.z = (v.z - mu) * inv * g.z + b.z;
    v.w = (v.w - mu) * inv * g.w + b.w;
    *(float4*)&out[(size_t)row * HID + tid * 4] = v;
}

// ============================================================
extern "C" void kernel_launch(void* const* d_in, const int* in_sizes, int n_in,
                              void* d_out, int out_size) {
    const float* x     = (const float*)d_in[0];
    const float* A     = (const float*)d_in[1];
    const float* B     = (const float*)d_in[2];
    const float* C     = (const float*)d_in[3];
    const float* D     = (const float*)d_in[4];
    const float* gamma = (const float*)d_in[5];
    const float* beta  = (const float*)d_in[6];
    float* out = (float*)d_out;
    (void)in_sizes; (void)n_in; (void)out_size;

    k_xB        <<<NROWS / 128, 256>>>(x, B);
    k_powers    <<<1, 256>>>(A);
    k_scan_local<<<NCHT / 8, 128>>>(A);
    k_carry     <<<1, 64>>>();
    k_fixup     <<<NROWS / 8, 128>>>();
    dim3 g3(HID / BN, NROWS / BM);
    k_main      <<<g3, 256>>>(x, C, D, out);
    k_ln        <<<NROWS, 256>>>(out, gamma, beta);
}

// round 3
// speedup vs baseline: 2.0438x; 2.0438x over previous
#include <cuda_runtime.h>
#include <cuda_bf16.h>
#include <cstdint>

#define BATCH 4
#define SEQ   4096
#define HID   1024
#define NST   16
#define NROWS (BATCH*SEQ)       // 16384
#define CHUNK 64
#define NCH   (SEQ/CHUNK)       // 64
#define NCHT  (BATCH*NCH)       // 256
#define LN_EPS 1e-5f

// ---- scratch (static device globals) ----
__device__ float g_xB[NROWS*NST];
__device__ float g_states[NROWS*NST];
__device__ float g_finals[NCHT*NST];
__device__ float g_carry[NCHT*NST];
__device__ float g_Apow[(CHUNK+1)*NST*NST];       // A^0..A^64
__device__ float g_Qpow[NCH*NST*NST];             // (A^64)^0..^63
__device__ __nv_bfloat16 g_xhi[(size_t)NROWS*HID];
__device__ __nv_bfloat16 g_xlo[(size_t)NROWS*HID];
__device__ __nv_bfloat16 g_Dhi[(size_t)HID*HID];
__device__ __nv_bfloat16 g_Dlo[(size_t)HID*HID];

// ================= PTX helpers (all non-'a' features: sm_80 baseline) ====
__device__ __forceinline__ uint32_t smem_u32(const void* p) {
    uint32_t a;
    asm("{ .reg .u64 t; cvta.to.shared.u64 t, %1; cvt.u32.u64 %0, t; }" : "=r"(a) : "l"(p));
    return a;
}
__device__ __forceinline__ void cp16(uint32_t dst, const void* src) {
    asm volatile("cp.async.cg.shared.global [%0], [%1], 16;" :: "r"(dst), "l"(src) : "memory");
}
__device__ __forceinline__ void cp_commit() {
    asm volatile("cp.async.commit_group;" ::: "memory");
}
__device__ __forceinline__ void cp_wait1() {
    asm volatile("cp.async.wait_group 1;" ::: "memory");
}
__device__ __forceinline__ void cp_wait0() {
    asm volatile("cp.async.wait_group 0;" ::: "memory");
}
__device__ __forceinline__ void ldsm4(uint32_t* r, uint32_t a) {
    asm volatile("ldmatrix.sync.aligned.m8n8.x4.shared.b16 {%0,%1,%2,%3}, [%4];"
                 : "=r"(r[0]), "=r"(r[1]), "=r"(r[2]), "=r"(r[3]) : "r"(a));
}
__device__ __forceinline__ void mma16816(float* c, const uint32_t* a, const uint32_t* b) {
    asm volatile(
        "mma.sync.aligned.m16n8k16.row.col.f32.bf16.bf16.f32 "
        "{%0,%1,%2,%3}, {%4,%5,%6,%7}, {%8,%9}, {%0,%1,%2,%3};"
        : "+f"(c[0]), "+f"(c[1]), "+f"(c[2]), "+f"(c[3])
        : "r"(a[0]), "r"(a[1]), "r"(a[2]), "r"(a[3]), "r"(b[0]), "r"(b[1]));
}
static __device__ __forceinline__ uint32_t swz(uint32_t x) { return x ^ ((x >> 3) & 0x70); }

// ============================================================
// K0: float -> bf16 hi/lo split
// ============================================================
__global__ __launch_bounds__(256) void k_cvt(const float* __restrict__ src,
                                             __nv_bfloat16* __restrict__ hi,
                                             __nv_bfloat16* __restrict__ lo, int n4) {
    int i = blockIdx.x * 256 + threadIdx.x;
    if (i >= n4) return;
    float4 v = ((const float4*)src)[i];
    __nv_bfloat16 h0 = __float2bfloat16_rn(v.x);
    __nv_bfloat16 h1 = __float2bfloat16_rn(v.y);
    __nv_bfloat16 h2 = __float2bfloat16_rn(v.z);
    __nv_bfloat16 h3 = __float2bfloat16_rn(v.w);
    __nv_bfloat16 l0 = __float2bfloat16_rn(v.x - __bfloat162float(h0));
    __nv_bfloat16 l1 = __float2bfloat16_rn(v.y - __bfloat162float(h1));
    __nv_bfloat16 l2 = __float2bfloat16_rn(v.z - __bfloat162float(h2));
    __nv_bfloat16 l3 = __float2bfloat16_rn(v.w - __bfloat162float(h3));
    __nv_bfloat162 ph0 = __nv_bfloat162(h0, h1), ph1 = __nv_bfloat162(h2, h3);
    __nv_bfloat162 pl0 = __nv_bfloat162(l0, l1), pl1 = __nv_bfloat162(l2, l3);
    ((uint2*)hi)[i] = make_uint2(*(uint32_t*)&ph0, *(uint32_t*)&ph1);
    ((uint2*)lo)[i] = make_uint2(*(uint32_t*)&pl0, *(uint32_t*)&pl1);
}

// ============================================================
// K1: xB[row,n] = sum_h x[row,h] * B[n,h]
// ============================================================
__global__ __launch_bounds__(256) void k_xB(const float* __restrict__ x,
                                            const float* __restrict__ B) {
    __shared__ float xs[128][33];
    __shared__ float Bs[NST][33];
    const int tid = threadIdx.x;
    const int rowbase = blockIdx.x * 128;
    const int n  = tid & 15;
    const int rg = tid >> 4;

    float acc[8];
#pragma unroll
    for (int i = 0; i < 8; i++) acc[i] = 0.f;

    for (int kb = 0; kb < HID; kb += 32) {
#pragma unroll
        for (int p = 0; p < 4; p++) {
            int idx = tid + p * 256;
            int r  = idx >> 3;
            int kq = (idx & 7) * 4;
            float4 v = *(const float4*)&x[(rowbase + r) * HID + kb + kq];
            xs[r][kq+0] = v.x; xs[r][kq+1] = v.y; xs[r][kq+2] = v.z; xs[r][kq+3] = v.w;
        }
        if (tid < 128) {
            int bn = tid >> 3;
            int kq = (tid & 7) * 4;
            float4 v = *(const float4*)&B[bn * HID + kb + kq];
            Bs[bn][kq+0] = v.x; Bs[bn][kq+1] = v.y; Bs[bn][kq+2] = v.z; Bs[bn][kq+3] = v.w;
        }
        __syncthreads();
#pragma unroll
        for (int k = 0; k < 32; k++) {
            float bv = Bs[n][k];
#pragma unroll
            for (int r = 0; r < 8; r++) acc[r] += xs[rg*8 + r][k] * bv;
        }
        __syncthreads();
    }
#pragma unroll
    for (int r = 0; r < 8; r++)
        g_xB[(rowbase + rg*8 + r) * NST + n] = acc[r];
}

// ============================================================
// K2a: per-chunk local scans
// ============================================================
__global__ __launch_bounds__(128) void k_scan_local(const float* __restrict__ A) {
    const int tid = threadIdx.x;
    const int lane16 = tid & 15;
    const int cid = blockIdx.x * 8 + (tid >> 4);
    const int b = cid >> 6;
    const int c = cid & (NCH - 1);
    const int gb = tid & 16;

    float Arow[NST];
#pragma unroll
    for (int k = 0; k < NST; k++) Arow[k] = A[lane16 * NST + k];

    float s = 0.f;
    const int base = (b * SEQ + c * CHUNK) * NST;
    for (int i = 0; i < CHUNK; i++) {
        float u  = g_xB[base + i * NST + lane16];
        float ns = u;
#pragma unroll
        for (int k = 0; k < NST; k++)
            ns += Arow[k] * __shfl_sync(0xffffffffu, s, gb | k, 32);
        s = ns;
        g_states[base + i * NST + lane16] = s;
    }
    g_finals[cid * NST + lane16] = s;
}

// ============================================================
// K2b: A^0..A^64, then Q_c = (A^64)^c
// ============================================================
__global__ __launch_bounds__(256) void k_powers(const float* __restrict__ A) {
    __shared__ float As[256], P[256];
    const int t = threadIdx.x;
    As[t] = A[t];
    float id = ((t >> 4) == (t & 15)) ? 1.f : 0.f;
    P[t] = id;
    g_Apow[t] = id;
    __syncthreads();
    const int n = t >> 4, m = t & 15;
    for (int j = 1; j <= CHUNK; j++) {
        float v = 0.f;
#pragma unroll
        for (int k = 0; k < NST; k++) v += As[n * NST + k] * P[k * NST + m];
        __syncthreads();
        P[t] = v;
        g_Apow[j * 256 + t] = v;
        __syncthreads();
    }
    As[t] = P[t];
    __syncthreads();
    P[t] = id;
    g_Qpow[t] = id;
    __syncthreads();
    for (int c = 1; c < NCH; c++) {
        float v = 0.f;
#pragma unroll
        for (int k = 0; k < NST; k++) v += P[n * NST + k] * As[k * NST + m];
        __syncthreads();
        P[t] = v;
        g_Qpow[c * 256 + t] = v;
        __syncthreads();
    }
}

// ============================================================
// K2c: carry[b,c] = sum_{j<c} Q_{c-1-j} @ finals[b,j]   (parallel)
// ============================================================
__global__ __launch_bounds__(256) void k_carry_par() {
    const int t = threadIdx.x;
    const int grp = t >> 4;
    const int n = t & 15;
    const int gid = blockIdx.x * 16 + grp;
    const int b = gid >> 6;
    const int c = gid & (NCH - 1);

    float acc = 0.f;
    for (int j = 0; j < c; j++) {
        const float* Qr = &g_Qpow[(c - 1 - j) * 256 + n * NST];
        const float* f  = &g_finals[(b * NCH + j) * NST];
#pragma unroll
        for (int k = 0; k < NST; k++) acc += Qr[k] * f[k];
    }
    g_carry[gid * NST + n] = acc;
}

// ============================================================
// K2d: fix-up: states += A^{i+1} @ carry
// ============================================================
__global__ __launch_bounds__(128) void k_fixup() {
    const int tid = threadIdx.x;
    const int n  = tid & 15;
    const int gb = tid & 16;
    const int row = blockIdx.x * 8 + (tid >> 4);
    const int b  = row >> 12;
    const int tt = row & (SEQ - 1);
    const int c  = tt >> 6;
    const int i  = tt & (CHUNK - 1);

    float cv = g_carry[(b * NCH + c) * NST + n];
    const float* Pr = &g_Apow[(i + 1) * 256 + n * NST];
    float v = 0.f;
#pragma unroll
    for (int k = 0; k < NST; k++)
        v += Pr[k] * __shfl_sync(0xffffffffu, cv, gb | k, 32);
    g_states[row * NST + n] += v;
}

// ============================================================
// K3: mma.sync bf16x3 GEMM: out = states @ C^T + x @ D^T
// 128x128 block tile, 8 warps (32x64 warp tile), BK=64, cp.async x2
// ============================================================
#define BKC 64
#define NKC (HID/BKC)          // 16
#define OFF_AH 0
#define OFF_AL 16384
#define OFF_BH 32768
#define OFF_BL 49152
#define STAGE  65536
#define OFF_SS (2*STAGE)                 // 131072: states tile 128x17 f32
#define OFF_CS (OFF_SS + 128*17*4)       // C tile 128x17 f32
#define DYN_SMEM (OFF_CS + 128*17*4)     // 148480

__global__ __launch_bounds__(256, 1)
void k_mma(const float* __restrict__ C, float* __restrict__ out) {
    extern __shared__ __align__(1024) char dsm[];
    const int tid  = threadIdx.x;
    const int lane = tid & 31;
    const int wid  = tid >> 5;
    const int wm   = wid & 3;        // 4 M groups of 32 rows
    const int wn   = wid >> 2;       // 2 N groups of 64 cols
    const int g    = lane >> 2;
    const int tig  = lane & 3;
    const int rowbase = blockIdx.y * 128;
    const int colbase = blockIdx.x * 128;
    const uint32_t sbase = smem_u32(dsm);
    float* Ss = (float*)(dsm + OFF_SS);
    float* Cs = (float*)(dsm + OFF_CS);

    // ---- issue chunk 0 loads ----
#pragma unroll
    for (int p = 0; p < 4; p++) {
        int idx = p * 256 + tid;
        int r = idx >> 3, c8 = (idx & 7) * 8;
        uint32_t so = swz((uint32_t)(r * 128 + c8 * 2));
        size_t gA = (size_t)(rowbase + r) * HID + c8;
        size_t gB = (size_t)(colbase + r) * HID + c8;
        cp16(sbase + OFF_AH + so, g_xhi + gA);
        cp16(sbase + OFF_AL + so, g_xlo + gA);
        cp16(sbase + OFF_BH + so, g_Dhi + gB);
        cp16(sbase + OFF_BL + so, g_Dlo + gB);
    }
    cp_commit();

    // ---- load states/C tiles (fp32 init path), overlapped with cp.async ----
#pragma unroll
    for (int q = 0; q < 2; q++) {
        int idx4 = tid + q * 256;          // 512 float4 per tile
        int r = idx4 >> 2, kq = (idx4 & 3) * 4;
        float4 s = *(const float4*)&g_states[(size_t)(rowbase + r) * NST + kq];
        float4 c = *(const float4*)&C[(size_t)(colbase + r) * NST + kq];
        Ss[r * 17 + kq + 0] = s.x; Ss[r * 17 + kq + 1] = s.y;
        Ss[r * 17 + kq + 2] = s.z; Ss[r * 17 + kq + 3] = s.w;
        Cs[r * 17 + kq + 0] = c.x; Cs[r * 17 + kq + 1] = c.y;
        Cs[r * 17 + kq + 2] = c.z; Cs[r * 17 + kq + 3] = c.w;
    }
    __syncthreads();

    // ---- init acc = states @ C^T (K=16, fp32 exact) ----
    float acc[2][8][4];
#pragma unroll
    for (int i = 0; i < 2; i++) {
        const int m0 = wm * 32 + i * 16 + g;
        float s0[16], s1[16];
#pragma unroll
        for (int k = 0; k < 16; k++) { s0[k] = Ss[m0 * 17 + k]; s1[k] = Ss[(m0 + 8) * 17 + k]; }
#pragma unroll
        for (int j = 0; j < 8; j++) {
            const int n0 = wn * 64 + j * 8 + tig * 2;
            float c0 = 0.f, c1 = 0.f, c2 = 0.f, c3 = 0.f;
#pragma unroll
            for (int k = 0; k < 16; k++) {
                float e0 = Cs[n0 * 17 + k], e1 = Cs[(n0 + 1) * 17 + k];
                c0 += s0[k] * e0; c1 += s0[k] * e1;
                c2 += s1[k] * e0; c3 += s1[k] * e1;
            }
            acc[i][j][0] = c0; acc[i][j][1] = c1; acc[i][j][2] = c2; acc[i][j][3] = c3;
        }
    }

    // ---- main K loop ----
    for (int c = 0; c < NKC; c++) {
        if (c + 1 < NKC) {
            const uint32_t sb = sbase + ((c + 1) & 1) * STAGE;
            const int kb = (c + 1) * BKC;
#pragma unroll
            for (int p = 0; p < 4; p++) {
                int idx = p * 256 + tid;
                int r = idx >> 3, c8 = (idx & 7) * 8;
                uint32_t so = swz((uint32_t)(r * 128 + c8 * 2));
                size_t gA = (size_t)(rowbase + r) * HID + kb + c8;
                size_t gB = (size_t)(colbase + r) * HID + kb + c8;
                cp16(sb + OFF_AH + so, g_xhi + gA);
                cp16(sb + OFF_AL + so, g_xlo + gA);
                cp16(sb + OFF_BH + so, g_Dhi + gB);
                cp16(sb + OFF_BL + so, g_Dlo + gB);
            }
            cp_commit();
            cp_wait1();
        } else {
            cp_wait0();
        }
        __syncthreads();

        const uint32_t sb = sbase + (c & 1) * STAGE;
#pragma unroll
        for (int ks = 0; ks < BKC / 16; ks++) {
            uint32_t aH[2][4], aL[2][4], bH[8][2], bL[8][2];
#pragma unroll
            for (int i = 0; i < 2; i++) {
                uint32_t off = swz((uint32_t)((wm * 32 + i * 16 + (lane & 15)) * 128 +
                                              (ks * 16 + (lane >> 4) * 8) * 2));
                ldsm4(aH[i], sb + OFF_AH + off);
                ldsm4(aL[i], sb + OFF_AL + off);
            }
#pragma unroll
            for (int p = 0; p < 4; p++) {
                uint32_t nloc = wn * 64 + p * 16 + ((lane >> 4) & 1) * 8 + (lane & 7);
                uint32_t kc = ks * 16 + ((lane >> 3) & 1) * 8;
                uint32_t off = swz(nloc * 128 + kc * 2);
                uint32_t rh[4], rl[4];
                ldsm4(rh, sb + OFF_BH + off);
                ldsm4(rl, sb + OFF_BL + off);
                bH[2*p][0] = rh[0]; bH[2*p][1] = rh[1]; bH[2*p+1][0] = rh[2]; bH[2*p+1][1] = rh[3];
                bL[2*p][0] = rl[0]; bL[2*p][1] = rl[1]; bL[2*p+1][0] = rl[2]; bL[2*p+1][1] = rl[3];
            }
#pragma unroll
            for (int i = 0; i < 2; i++)
#pragma unroll
                for (int j = 0; j < 8; j++) {
                    mma16816(acc[i][j], aH[i], bH[j]);
                    mma16816(acc[i][j], aH[i], bL[j]);
                    mma16816(acc[i][j], aL[i], bH[j]);
                }
        }
        __syncthreads();
    }

    // ---- epilogue: pure stores ----
#pragma unroll
    for (int i = 0; i < 2; i++) {
        const int m0 = rowbase + wm * 32 + i * 16 + g;
#pragma unroll
        for (int j = 0; j < 8; j++) {
            const int n0 = colbase + wn * 64 + j * 8 + tig * 2;
            *(float2*)&out[(size_t)m0 * HID + n0]       = make_float2(acc[i][j][0], acc[i][j][1]);
            *(float2*)&out[(size_t)(m0 + 8) * HID + n0] = make_float2(acc[i][j][2], acc[i][j][3]);
        }
    }
}

// ============================================================
// K4: LayerNorm in place
// ============================================================
__global__ __launch_bounds__(256) void k_ln(float* __restrict__ out,
                                            const float* __restrict__ gamma,
                                            const float* __restrict__ beta) {
    __shared__ float rs[8], rs2[8];
    const int row = blockIdx.x;
    const int tid = threadIdx.x;

    float4 v = *(const float4*)&out[(size_t)row * HID + tid * 4];
    float s  = v.x + v.y + v.z + v.w;
    float s2 = v.x*v.x + v.y*v.y + v.z*v.z + v.w*v.w;
#pragma unroll
    for (int o = 16; o > 0; o >>= 1) {
        s  += __shfl_down_sync(0xffffffffu, s,  o);
        s2 += __shfl_down_sync(0xffffffffu, s2, o);
    }
    if ((tid & 31) == 0) { rs[tid >> 5] = s; rs2[tid >> 5] = s2; }
    __syncthreads();
    float ts = 0.f, ts2 = 0.f;
#pragma unroll
    for (int i = 0; i < 8; i++) { ts += rs[i]; ts2 += rs2[i]; }

    const float mu  = ts * (1.f / HID);
    const float var = ts2 * (1.f / HID) - mu * mu;
    const float inv = rsqrtf(var + LN_EPS);

    float4 gm = *(const float4*)&gamma[tid * 4];
    float4 bt = *(const float4*)&beta[tid * 4];
    v.x = (v.x - mu) * inv * gm.x + bt.x;
    v.y = (v.y - mu) * inv * gm.y + bt.y;
    v.z = (v.z - mu) * inv * gm.z + bt.z;
    v.w = (v.w - mu) * inv * gm.w + bt.w;
    *(float4*)&out[(size_t)row * HID + tid * 4] = v;
}

// ============================================================
extern "C" void kernel_launch(void* const* d_in, const int* in_sizes, int n_in,
                              void* d_out, int out_size) {
    const float* x     = (const float*)d_in[0];
    const float* A     = (const float*)d_in[1];
    const float* B     = (const float*)d_in[2];
    const float* C     = (const float*)d_in[3];
    const float* D     = (const float*)d_in[4];
    const float* gamma = (const float*)d_in[5];
    const float* beta  = (const float*)d_in[6];
    float* out = (float*)d_out;
    (void)in_sizes; (void)n_in; (void)out_size;

    cudaFuncSetAttribute(k_mma, cudaFuncAttributeMaxDynamicSharedMemorySize, DYN_SMEM);

    __nv_bfloat16 *xhi_p, *xlo_p, *dhi_p, *dlo_p;
    cudaGetSymbolAddress((void**)&xhi_p, g_xhi);
    cudaGetSymbolAddress((void**)&xlo_p, g_xlo);
    cudaGetSymbolAddress((void**)&dhi_p, g_Dhi);
    cudaGetSymbolAddress((void**)&dlo_p, g_Dlo);

    k_cvt<<<(NROWS * HID / 4 + 255) / 256, 256>>>(x, xhi_p, xlo_p, NROWS * HID / 4);
    k_cvt<<<(HID * HID / 4 + 255) / 256, 256>>>(D, dhi_p, dlo_p, HID * HID / 4);

    k_xB        <<<NROWS / 128, 256>>>(x, B);
    k_powers    <<<1, 256>>>(A);
    k_scan_local<<<NCHT / 8, 128>>>(A);
    k_carry_par <<<NCHT / 16, 256>>>();
    k_fixup     <<<NROWS / 8, 128>>>();

    dim3 g3(HID / 128, NROWS / 128);
    k_mma       <<<g3, 256, DYN_SMEM>>>(C, out);
    k_ln        <<<NROWS, 256>>>(out, gamma, beta);
}